// round 16
// baseline (speedup 1.0000x reference)
#include <cuda_runtime.h>
#include <cuda_bf16.h>

#define NN 50000
#define EE 600000
#define LN_EPS 1e-5f

typedef unsigned long long ull;
typedef unsigned int u32;

// ---- scratch (device globals; no allocations allowed) ----
__device__ float g_msg[(size_t)NN * 128];
__device__ float g_h[(size_t)NN * 128];
__device__ float g_m[(size_t)50176 * 128];   // per-thread m stash (padded to tile mult)
__device__ int   g_rowptr[NN + 1];
__device__ int   g_counts[NN];
__device__ int   g_cursor[NN];
__device__ int   g_srclist[EE];
__device__ int   g_partials[256];
// row-major bf16 hi/lo weights: [layer][matrix 0..2][hi/lo][128*128]
__device__ __align__(16) __nv_bfloat16 g_wprep[2][3][2][16384];

// ============================ helpers ============================

__device__ __forceinline__ u32 smem_u32(const void* p) {
    u32 a;
    asm("{ .reg .u64 t; cvta.to.shared.u64 t, %1; cvt.u32.u64 %0, t; }" : "=r"(a) : "l"(p));
    return a;
}
__device__ __forceinline__ void ldsm_x4(u32& r0, u32& r1, u32& r2, u32& r3, u32 addr) {
    asm volatile("ldmatrix.sync.aligned.m8n8.x4.shared.b16 {%0,%1,%2,%3}, [%4];"
                 : "=r"(r0), "=r"(r1), "=r"(r2), "=r"(r3) : "r"(addr));
}
__device__ __forceinline__ void mma16816(float* d, const u32* a, u32 b0, u32 b1) {
    asm volatile(
        "mma.sync.aligned.m16n8k16.row.col.f32.bf16.bf16.f32 "
        "{%0,%1,%2,%3}, {%4,%5,%6,%7}, {%8,%9}, {%0,%1,%2,%3};"
        : "+f"(d[0]), "+f"(d[1]), "+f"(d[2]), "+f"(d[3])
        : "r"(a[0]), "r"(a[1]), "r"(a[2]), "r"(a[3]), "r"(b0), "r"(b1));
}

// ---- packed f32x2 helpers ----
__device__ __forceinline__ ull ffma2(ull a, ull b, ull c) {
    ull d;
    asm("fma.rn.f32x2 %0, %1, %2, %3;" : "=l"(d) : "l"(a), "l"(b), "l"(c));
    return d;
}
__device__ __forceinline__ ull pack2(float x) {
    ull d;
    asm("mov.b64 %0, {%1, %1};" : "=l"(d) : "f"(x));
    return d;
}
__device__ __forceinline__ float2 unpack2(ull v) {
    float2 r;
    asm("mov.b64 {%0, %1}, %2;" : "=f"(r.x), "=f"(r.y) : "l"(v));
    return r;
}

// ============================ CSR build ============================

__global__ void k_zero(int n) {
    int i = blockIdx.x * blockDim.x + threadIdx.x;
    if (i < n) { g_counts[i] = 0; g_cursor[i] = 0; }
}
__global__ void k_count(const int* __restrict__ dst, int e) {
    int i = blockIdx.x * blockDim.x + threadIdx.x;
    if (i < e) atomicAdd(&g_counts[dst[i]], 1);
}

__global__ void k_scan_a(int n) {
    int tid = threadIdx.x, lane = tid & 31, w = tid >> 5;
    int i = blockIdx.x * 256 + tid;
    int v = (i < n) ? g_counts[i] : 0;
    #pragma unroll
    for (int o = 16; o; o >>= 1) v += __shfl_xor_sync(0xffffffffu, v, o);
    __shared__ int ws[8];
    if (lane == 0) ws[w] = v;
    __syncthreads();
    if (tid == 0) {
        int s = 0;
        #pragma unroll
        for (int q = 0; q < 8; q++) s += ws[q];
        g_partials[blockIdx.x] = s;
    }
}

__global__ void k_scan_b(int nb) {
    int tid = threadIdx.x, lane = tid & 31, w = tid >> 5;
    int v = (tid < nb) ? g_partials[tid] : 0;
    int x = v;
    #pragma unroll
    for (int o = 1; o < 32; o <<= 1) {
        int t = __shfl_up_sync(0xffffffffu, x, o);
        if (lane >= o) x += t;
    }
    __shared__ int ws[8];
    if (lane == 31) ws[w] = x;
    __syncthreads();
    if (w == 0) {
        int y = (lane < 8) ? ws[lane] : 0;
        #pragma unroll
        for (int o = 1; o < 8; o <<= 1) {
            int t = __shfl_up_sync(0xffffffffu, y, o);
            if (lane >= o) y += t;
        }
        if (lane < 8) ws[lane] = y;
    }
    __syncthreads();
    int incl = x + (w ? ws[w - 1] : 0);
    if (tid < nb) g_partials[tid] = incl - v;   // exclusive
}

__global__ void k_scan_c(int n, int e) {
    int tid = threadIdx.x, lane = tid & 31, w = tid >> 5;
    int i = blockIdx.x * 256 + tid;
    int v = (i < n) ? g_counts[i] : 0;
    int x = v;
    #pragma unroll
    for (int o = 1; o < 32; o <<= 1) {
        int t = __shfl_up_sync(0xffffffffu, x, o);
        if (lane >= o) x += t;
    }
    __shared__ int ws[8];
    if (lane == 31) ws[w] = x;
    __syncthreads();
    if (w == 0) {
        int y = (lane < 8) ? ws[lane] : 0;
        #pragma unroll
        for (int o = 1; o < 8; o <<= 1) {
            int t = __shfl_up_sync(0xffffffffu, y, o);
            if (lane >= o) y += t;
        }
        if (lane < 8) ws[lane] = y;
    }
    __syncthreads();
    int incl = x + (w ? ws[w - 1] : 0);
    int excl = incl - v + g_partials[blockIdx.x];
    if (i < n) g_rowptr[i] = excl;
    if (i == 0 && blockIdx.x == 0) g_rowptr[n] = e;
}

__global__ void k_fill(const int* __restrict__ src, const int* __restrict__ dst, int e) {
    int i = blockIdx.x * blockDim.x + threadIdx.x;
    if (i < e) {
        int d = dst[i];
        int slot = g_rowptr[d] + atomicAdd(&g_cursor[d], 1);
        g_srclist[slot] = src[i];
    }
}

// ==================== weight prep: fp32 -> row-major bf16 hi/lo ====================

__global__ void k_prep(const float* __restrict__ W1, const float* __restrict__ F1,
                       const float* __restrict__ W2, const float* __restrict__ F2) {
    int b = blockIdx.x;           // 0..5
    int layer = b / 3, m = b % 3;
    const float* src;
    if (layer == 0) src = (m == 0) ? W1 : (F1 + (m - 1) * 16384);
    else            src = (m == 0) ? W2 : (F2 + (m - 1) * 16384);
    __nv_bfloat16* dhi = &g_wprep[layer][m][0][0];
    __nv_bfloat16* dlo = &g_wprep[layer][m][1][0];
    for (int i = threadIdx.x; i < 16384; i += blockDim.x) {
        float v = src[i];
        __nv_bfloat16 h = __float2bfloat16(v);
        __nv_bfloat16 l = __float2bfloat16(v - __bfloat162float(h));
        dhi[i] = h;
        dlo[i] = l;
    }
}

// ============================ FiLM GEMM (mma.sync bf16, cp.async pipelined) ============
// CTA: 128 nodes x 384 outputs, 8 warps, each warp 16 rows x 128 cols.
// D = Ah*Bh + Al*Bh + Ah*Bl per matrix. m (matrix 0 result) stashed to g_m (global,
// thread-private round-trip, L2-hot); gamma/beta in regs. msg = relu(gamma*m + beta).
// B matrices double-buffered via cp.async: B0,B1 prefetch before X-convert; B2 during gemm1.

// smem layout (bytes)
#define SA_HI 0
#define SA_LO 32768
#define SB0   65536
#define SB1   131072
#define SMEM_MMA 196608

// chunk swizzle: 16B chunks, pitch 256B (16 chunks/row)
__device__ __forceinline__ u32 sw_addr(u32 base, int row, int chunk) {
    return base + (u32)row * 256u + (u32)((chunk ^ (row & 7)) << 4);
}

// async-stage one 128x128 bf16 matrix (32KB) into swizzled smem
__device__ __forceinline__ void stage32k_async(u32 sdst, const __nv_bfloat16* src, int tid) {
    const char* g = (const char*)src;
    #pragma unroll
    for (int it = 0; it < 8; it++) {
        int idx = tid + it * 256;          // 0..2047 chunks
        int row = idx >> 4, c = idx & 15;
        asm volatile("cp.async.cg.shared.global [%0], [%1], 16;"
                     :: "r"(sw_addr(sdst, row, c)), "l"(g + (size_t)idx * 16) : "memory");
    }
}
__device__ __forceinline__ void cpasync_commit() {
    asm volatile("cp.async.commit_group;" ::: "memory");
}
#define CPASYNC_WAIT(N) asm volatile("cp.async.wait_group %0;" :: "n"(N) : "memory")

// compute one 128x128 matrix product into acc[16][4]
__device__ __forceinline__ void gemm_mat(float acc[16][4], u32 sAhi, u32 sAlo,
                                         u32 sBhi, u32 sBlo, int w, int lane) {
    int tile = lane >> 3;                 // 0..3
    int rA = 16 * w + (tile & 1) * 8 + (lane & 7);
    int rAs = rA & 7;
    int hiA = tile >> 1;
    u32 aHiRow = sAhi + (u32)rA * 256u;
    u32 aLoRow = sAlo + (u32)rA * 256u;
    int rB = (tile & 1) * 8 + (lane & 7);
    int rBs = rB & 7;
    int hiB = tile >> 1;

    #pragma unroll
    for (int kt = 0; kt < 8; kt++) {
        u32 ah[4], al[4];
        u32 aoff = (u32)(((kt * 2 + hiA) ^ rAs) << 4);
        ldsm_x4(ah[0], ah[1], ah[2], ah[3], aHiRow + aoff);
        ldsm_x4(al[0], al[1], al[2], al[3], aLoRow + aoff);
        #pragma unroll
        for (int nt2 = 0; nt2 < 8; nt2++) {
            int rowB = nt2 * 16 + rB;
            u32 boff = (u32)rowB * 256u + (u32)(((kt * 2 + hiB) ^ rBs) << 4);
            u32 bh[4], bl[4];
            ldsm_x4(bh[0], bh[1], bh[2], bh[3], sBhi + boff);
            ldsm_x4(bl[0], bl[1], bl[2], bl[3], sBlo + boff);
            mma16816(acc[2 * nt2 + 0], ah, bh[0], bh[2]);
            mma16816(acc[2 * nt2 + 0], al, bh[0], bh[2]);
            mma16816(acc[2 * nt2 + 0], ah, bl[0], bl[2]);
            mma16816(acc[2 * nt2 + 1], ah, bh[1], bh[3]);
            mma16816(acc[2 * nt2 + 1], al, bh[1], bh[3]);
            mma16816(acc[2 * nt2 + 1], ah, bl[1], bl[3]);
        }
    }
}

__global__ void __launch_bounds__(256, 1)
k_film_mma(const float* __restrict__ Xext, int use_internal, int layer, int n) {
    extern __shared__ char sm[];
    u32 sb = smem_u32(sm);
    int tid = threadIdx.x, w = tid >> 5, lane = tid & 31;
    const float* X = use_internal ? g_h : Xext;
    int nbase = blockIdx.x * 128;
    int ntail = n - nbase; if (ntail > 128) ntail = 128;

    const __nv_bfloat16* prep = &g_wprep[layer][0][0][0];

    // ---- prefetch B0 (group 0) and B1 (group 1) ----
    stage32k_async(sb + SB0, prep, tid);
    stage32k_async(sb + SB0 + 32768, prep + 16384, tid);
    cpasync_commit();
    stage32k_async(sb + SB1, prep + 2 * 16384, tid);
    stage32k_async(sb + SB1 + 32768, prep + 3 * 16384, tid);
    cpasync_commit();

    // zero A smem only for the tail tile
    if (ntail < 128) {
        #pragma unroll
        for (int i = 0; i < 16; i++) {
            asm volatile("st.shared.v4.b32 [%0], {%1,%1,%1,%1};"
                         :: "r"(sb + SA_HI + (u32)(tid * 16 + i * 4096)), "r"(0u));
        }
    }

    // ---- convert X tile to bf16 hi/lo, swizzled (overlaps B prefetch) ----
    #pragma unroll
    for (int it = 0; it < 8; it++) {
        int idx = tid + it * 256;          // 2048 chunks
        int row = idx >> 4, c = idx & 15;
        if (row < ntail) {
            const float* xp = X + (size_t)(nbase + row) * 128 + c * 8;
            float4 v0 = *(const float4*)xp;
            float4 v1 = *(const float4*)(xp + 4);
            float f[8] = {v0.x, v0.y, v0.z, v0.w, v1.x, v1.y, v1.z, v1.w};
            u32 hp[4], lp[4];
            #pragma unroll
            for (int q = 0; q < 4; q++) {
                __nv_bfloat16 h0 = __float2bfloat16(f[2 * q]);
                __nv_bfloat16 h1 = __float2bfloat16(f[2 * q + 1]);
                __nv_bfloat16 l0 = __float2bfloat16(f[2 * q] - __bfloat162float(h0));
                __nv_bfloat16 l1 = __float2bfloat16(f[2 * q + 1] - __bfloat162float(h1));
                __nv_bfloat162 hh; hh.x = h0; hh.y = h1;
                __nv_bfloat162 ll; ll.x = l0; ll.y = l1;
                hp[q] = *(u32*)&hh;
                lp[q] = *(u32*)&ll;
            }
            asm volatile("st.shared.v4.b32 [%0], {%1,%2,%3,%4};"
                         :: "r"(sw_addr(sb + SA_HI, row, c)), "r"(hp[0]), "r"(hp[1]), "r"(hp[2]), "r"(hp[3]));
            asm volatile("st.shared.v4.b32 [%0], {%1,%2,%3,%4};"
                         :: "r"(sw_addr(sb + SA_LO, row, c)), "r"(lp[0]), "r"(lp[1]), "r"(lp[2]), "r"(lp[3]));
        }
    }

    int r0 = 16 * w + (lane >> 2);
    int c0 = 2 * (lane & 3);
    float* mpA = g_m + (size_t)(nbase + r0) * 128;
    float* mpB = g_m + (size_t)(nbase + r0 + 8) * 128;

    // ---- matrix 0 (W -> m): wait B0, compute, stash m to g_m ----
    CPASYNC_WAIT(1);
    __syncthreads();
    {
        float acc[16][4];
        #pragma unroll
        for (int i = 0; i < 16; i++) { acc[i][0] = acc[i][1] = acc[i][2] = acc[i][3] = 0.f; }
        gemm_mat(acc, sb + SA_HI, sb + SA_LO, sb + SB0, sb + SB0 + 32768, w, lane);
        #pragma unroll
        for (int nt = 0; nt < 16; nt++) {
            *(float2*)(mpA + nt * 8 + c0) = make_float2(acc[nt][0], acc[nt][1]);
            *(float2*)(mpB + nt * 8 + c0) = make_float2(acc[nt][2], acc[nt][3]);
        }
    }
    __syncthreads();   // all warps done reading B0 buffer

    // ---- prefetch B2 into buffer 0 (group 2) ----
    stage32k_async(sb + SB0, prep + 4 * 16384, tid);
    stage32k_async(sb + SB0 + 32768, prep + 5 * 16384, tid);
    cpasync_commit();

    // ---- matrix 1 (gamma): wait B1 ----
    CPASYNC_WAIT(1);
    __syncthreads();
    float accG[16][4];
    #pragma unroll
    for (int i = 0; i < 16; i++) { accG[i][0] = accG[i][1] = accG[i][2] = accG[i][3] = 0.f; }
    gemm_mat(accG, sb + SA_HI, sb + SA_LO, sb + SB1, sb + SB1 + 32768, w, lane);

    // ---- matrix 2 (beta): wait B2 ----
    CPASYNC_WAIT(0);
    __syncthreads();
    float accB[16][4];
    #pragma unroll
    for (int i = 0; i < 16; i++) { accB[i][0] = accB[i][1] = accB[i][2] = accB[i][3] = 0.f; }
    gemm_mat(accB, sb + SA_HI, sb + SA_LO, sb + SB0, sb + SB0 + 32768, w, lane);

    // ---- epilogue: msg = relu(gamma*m + beta), m re-read from g_m (L2-hot, own writes) ----
    bool okA = (r0 < ntail), okB = (r0 + 8 < ntail);
    float* outA = g_msg + (size_t)(nbase + r0) * 128;
    float* outB = g_msg + (size_t)(nbase + r0 + 8) * 128;
    #pragma unroll
    for (int nt = 0; nt < 16; nt++) {
        float2 mA = *(float2*)(mpA + nt * 8 + c0);
        float2 mB = *(float2*)(mpB + nt * 8 + c0);
        if (okA) {
            float2 o;
            o.x = fmaxf(fmaf(accG[nt][0], mA.x, accB[nt][0]), 0.f);
            o.y = fmaxf(fmaf(accG[nt][1], mA.y, accB[nt][1]), 0.f);
            *(float2*)(outA + nt * 8 + c0) = o;
        }
        if (okB) {
            float2 o;
            o.x = fmaxf(fmaf(accG[nt][2], mB.x, accB[nt][2]), 0.f);
            o.y = fmaxf(fmaf(accG[nt][3], mB.y, accB[nt][3]), 0.f);
            *(float2*)(outB + nt * 8 + c0) = o;
        }
    }
}

// ===================== gather (segment sum) + layernorm -> g_h =====================
// one warp per destination node; 4-way unrolled edge loop for MLP.

__global__ void __launch_bounds__(256)
k_gather_ln(const float* __restrict__ gw, const float* __restrict__ bw, int n) {
    int node = blockIdx.x * 8 + (threadIdx.x >> 5);
    int lane = threadIdx.x & 31;
    if (node >= n) return;
    int beg = g_rowptr[node], end = g_rowptr[node + 1];
    const float4* __restrict__ msg4 = (const float4*)g_msg;
    float4 a0 = make_float4(0.f, 0.f, 0.f, 0.f), a1 = a0, a2 = a0, a3 = a0;
    int i = beg;
    for (; i + 4 <= end; i += 4) {
        int s0 = g_srclist[i + 0], s1 = g_srclist[i + 1];
        int s2 = g_srclist[i + 2], s3 = g_srclist[i + 3];
        float4 v0 = __ldg(&msg4[(size_t)s0 * 32 + lane]);
        float4 v1 = __ldg(&msg4[(size_t)s1 * 32 + lane]);
        float4 v2 = __ldg(&msg4[(size_t)s2 * 32 + lane]);
        float4 v3 = __ldg(&msg4[(size_t)s3 * 32 + lane]);
        a0.x += v0.x; a0.y += v0.y; a0.z += v0.z; a0.w += v0.w;
        a1.x += v1.x; a1.y += v1.y; a1.z += v1.z; a1.w += v1.w;
        a2.x += v2.x; a2.y += v2.y; a2.z += v2.z; a2.w += v2.w;
        a3.x += v3.x; a3.y += v3.y; a3.z += v3.z; a3.w += v3.w;
    }
    for (; i < end; i++) {
        int s = g_srclist[i];
        float4 v = __ldg(&msg4[(size_t)s * 32 + lane]);
        a0.x += v.x; a0.y += v.y; a0.z += v.z; a0.w += v.w;
    }
    float4 a;
    a.x = (a0.x + a1.x) + (a2.x + a3.x);
    a.y = (a0.y + a1.y) + (a2.y + a3.y);
    a.z = (a0.z + a1.z) + (a2.z + a3.z);
    a.w = (a0.w + a1.w) + (a2.w + a3.w);
    float loc = a.x + a.y + a.z + a.w;
    #pragma unroll
    for (int o = 16; o; o >>= 1) loc += __shfl_xor_sync(0xffffffffu, loc, o);
    float mu = loc * (1.0f / 128.0f);
    float d0 = a.x - mu, d1 = a.y - mu, d2 = a.z - mu, d3 = a.w - mu;
    float l2 = d0 * d0 + d1 * d1 + d2 * d2 + d3 * d3;
    #pragma unroll
    for (int o = 16; o; o >>= 1) l2 += __shfl_xor_sync(0xffffffffu, l2, o);
    float rs = rsqrtf(l2 * (1.0f / 128.0f) + LN_EPS);
    float4 gg = __ldg(&((const float4*)gw)[lane]);
    float4 bb = __ldg(&((const float4*)bw)[lane]);
    float4 o4;
    o4.x = d0 * rs * gg.x + bb.x;
    o4.y = d1 * rs * gg.y + bb.y;
    o4.z = d2 * rs * gg.z + bb.z;
    o4.w = d3 * rs * gg.w + bb.w;
    ((float4*)g_h)[(size_t)node * 32 + lane] = o4;
}

// ===== fused gather + layernorm + projection: out = sigmoid(LN(gather(msg)) @ Wp.T + bp) =====
// 32 nodes/block: phase 1 gather+LN into smem h tile; phase 2 proj (FFMA2) from smem.

#define SMEM_GLP ((128 * 64 + 32 * 128) * 4)   // sWp k-major + h tile = 49152 B

__global__ void __launch_bounds__(256)
k_gather_ln_proj(const float* __restrict__ gw, const float* __restrict__ bw,
                 const float* __restrict__ Wp, const float* __restrict__ bp,
                 float* __restrict__ out, int n) {
    extern __shared__ float smf[];
    float* sWp = smf;                // [128 k][64 j]
    float* sH = smf + 128 * 64;      // [32][128]
    int t = threadIdx.x, w = t >> 5, lane = t & 31;
    int nbase = blockIdx.x * 32;

    // ---- stage Wp k-major (as in k_proj) ----
    {
        int j = t & 63, seg = t >> 6;
        const float4* w4 = (const float4*)(Wp + (size_t)j * 128);
        #pragma unroll
        for (int kk = 0; kk < 8; kk++) {
            int q = seg * 8 + kk;
            float4 v = w4[q];
            int k = q * 4;
            sWp[(k + 0) * 64 + j] = v.x;
            sWp[(k + 1) * 64 + j] = v.y;
            sWp[(k + 2) * 64 + j] = v.z;
            sWp[(k + 3) * 64 + j] = v.w;
        }
    }

    // ---- phase 1: gather + LN for 4 nodes per warp -> sH ----
    float4 gg = __ldg(&((const float4*)gw)[lane]);
    float4 bb = __ldg(&((const float4*)bw)[lane]);
    const float4* __restrict__ msg4 = (const float4*)g_msg;
    #pragma unroll
    for (int q = 0; q < 4; q++) {
        int row = w * 4 + q;
        int node = nbase + row;
        if (node < n) {
            int beg = g_rowptr[node], end = g_rowptr[node + 1];
            float4 a0 = make_float4(0.f, 0.f, 0.f, 0.f), a1 = a0, a2 = a0, a3 = a0;
            int i = beg;
            for (; i + 4 <= end; i += 4) {
                int s0 = g_srclist[i + 0], s1 = g_srclist[i + 1];
                int s2 = g_srclist[i + 2], s3 = g_srclist[i + 3];
                float4 v0 = __ldg(&msg4[(size_t)s0 * 32 + lane]);
                float4 v1 = __ldg(&msg4[(size_t)s1 * 32 + lane]);
                float4 v2 = __ldg(&msg4[(size_t)s2 * 32 + lane]);
                float4 v3 = __ldg(&msg4[(size_t)s3 * 32 + lane]);
                a0.x += v0.x; a0.y += v0.y; a0.z += v0.z; a0.w += v0.w;
                a1.x += v1.x; a1.y += v1.y; a1.z += v1.z; a1.w += v1.w;
                a2.x += v2.x; a2.y += v2.y; a2.z += v2.z; a2.w += v2.w;
                a3.x += v3.x; a3.y += v3.y; a3.z += v3.z; a3.w += v3.w;
            }
            for (; i < end; i++) {
                int s = g_srclist[i];
                float4 v = __ldg(&msg4[(size_t)s * 32 + lane]);
                a0.x += v.x; a0.y += v.y; a0.z += v.z; a0.w += v.w;
            }
            float4 a;
            a.x = (a0.x + a1.x) + (a2.x + a3.x);
            a.y = (a0.y + a1.y) + (a2.y + a3.y);
            a.z = (a0.z + a1.z) + (a2.z + a3.z);
            a.w = (a0.w + a1.w) + (a2.w + a3.w);
            float loc = a.x + a.y + a.z + a.w;
            #pragma unroll
            for (int o = 16; o; o >>= 1) loc += __shfl_xor_sync(0xffffffffu, loc, o);
            float mu = loc * (1.0f / 128.0f);
            float d0 = a.x - mu, d1 = a.y - mu, d2 = a.z - mu, d3 = a.w - mu;
            float l2 = d0 * d0 + d1 * d1 + d2 * d2 + d3 * d3;
            #pragma unroll
            for (int o = 16; o; o >>= 1) l2 += __shfl_xor_sync(0xffffffffu, l2, o);
            float rs = rsqrtf(l2 * (1.0f / 128.0f) + LN_EPS);
            float4 o4;
            o4.x = d0 * rs * gg.x + bb.x;
            o4.y = d1 * rs * gg.y + bb.y;
            o4.z = d2 * rs * gg.z + bb.z;
            o4.w = d3 * rs * gg.w + bb.w;
            *(float4*)(sH + row * 128 + 4 * lane) = o4;
        }
    }
    __syncthreads();

    // ---- phase 2: proj 4 nodes per warp from sH ----
    int n0 = w * 4;
    const float* sHb = sH + n0 * 128;
    ull acc[4];
    #pragma unroll
    for (int i = 0; i < 4; i++) acc[i] = 0ull;
    #pragma unroll 4
    for (int k = 0; k < 128; k++) {
        ull wv = *(const ull*)(sWp + k * 64 + 2 * lane);
        #pragma unroll
        for (int i = 0; i < 4; i++)
            acc[i] = ffma2(pack2(sHb[i * 128 + k]), wv, acc[i]);
    }
    float2 bv = ((const float2*)bp)[lane];
    #pragma unroll
    for (int i = 0; i < 4; i++) {
        int node = nbase + n0 + i;
        if (node < n) {
            float2 s = unpack2(acc[i]);
            float v0 = 1.0f / (1.0f + __expf(-(s.x + bv.x)));
            float v1 = 1.0f / (1.0f + __expf(-(s.y + bv.y)));
            *(float2*)(out + (size_t)node * 64 + 2 * lane) = make_float2(v0, v1);
        }
    }
}

// ============================ launch ============================

extern "C" void kernel_launch(void* const* d_in, const int* in_sizes, int n_in,
                              void* d_out, int out_size) {
    const float* feats = (const float*)d_in[0];
    const int*   src   = (const int*)d_in[1];
    const int*   dst   = (const int*)d_in[2];
    const float* W1    = (const float*)d_in[3];
    const float* F1    = (const float*)d_in[4];
    const float* g1    = (const float*)d_in[5];
    const float* b1    = (const float*)d_in[6];
    const float* W2    = (const float*)d_in[7];
    const float* F2    = (const float*)d_in[8];
    const float* g2    = (const float*)d_in[9];
    const float* b2    = (const float*)d_in[10];
    const float* Wp    = (const float*)d_in[11];
    const float* bp    = (const float*)d_in[12];
    float* out = (float*)d_out;

    int n = in_sizes[0] / 128;   // 50000
    int e = in_sizes[1];         // 600000

    cudaFuncSetAttribute(k_film_mma, cudaFuncAttributeMaxDynamicSharedMemorySize, SMEM_MMA);
    cudaFuncSetAttribute(k_gather_ln_proj, cudaFuncAttributeMaxDynamicSharedMemorySize, SMEM_GLP);

    int mtiles = (n + 127) / 128;
    int nb = (n + 255) / 256;    // scan blocks (196)

    // Side stream + fork/join events (created once on first, uncaptured call).
    static cudaStream_t s2 = nullptr;
    static cudaEvent_t evFork = nullptr, evJoin = nullptr;
    if (!s2) {
        cudaStreamCreateWithFlags(&s2, cudaStreamNonBlocking);
        cudaEventCreateWithFlags(&evFork, cudaEventDisableTiming);
        cudaEventCreateWithFlags(&evJoin, cudaEventDisableTiming);
    }

    // ---- fork: CSR build on side stream (independent of prep/film1) ----
    cudaEventRecord(evFork, 0);
    cudaStreamWaitEvent(s2, evFork, 0);
    k_zero<<<(n + 255) / 256, 256, 0, s2>>>(n);
    k_count<<<(e + 255) / 256, 256, 0, s2>>>(dst, e);
    k_scan_a<<<nb, 256, 0, s2>>>(n);
    k_scan_b<<<1, 256, 0, s2>>>(nb);
    k_scan_c<<<nb, 256, 0, s2>>>(n, e);
    k_fill<<<(e + 255) / 256, 256, 0, s2>>>(src, dst, e);
    cudaEventRecord(evJoin, s2);

    // ---- main stream: weight prep + layer-1 GEMM (overlaps CSR) ----
    k_prep<<<6, 256>>>(W1, F1, W2, F2);
    k_film_mma<<<mtiles, 256, SMEM_MMA>>>(feats, 0, 0, n);

    // ---- join: gather needs both msg (main) and CSR (side) ----
    cudaStreamWaitEvent(0, evJoin, 0);

    k_gather_ln<<<(n + 7) / 8, 256>>>(g1, b1, n);
    // layer 2
    k_film_mma<<<mtiles, 256, SMEM_MMA>>>(nullptr, 1, 1, n);
    // fused gather + LN + projection
    k_gather_ln_proj<<<(n + 31) / 32, 256, SMEM_GLP>>>(g2, b2, Wp, bp, out, n);
}